// round 3
// baseline (speedup 1.0000x reference)
#include <cuda_runtime.h>
#include <math.h>

// Problem dims
#define BB   256
#define CIN  32
#define HW   1024          // 32*32
#define PP   192
#define COUT 32
#define NPIX (BB*HW)       // 262144
#define NCNT 262144.0f
#define EPSF 1e-5f

// ---------------- scratch (device globals; no allocation allowed) ----------
__device__ float g_y1[BB*PP*HW];     // stage1 raw conv output (NCHW)
__device__ float g_y2[BB*PP*HW];     // stage2 raw conv output
__device__ float g_y3[BB*COUT*HW];   // stage3 raw conv output
__device__ float g_W1[128*PP];       // [k=j*32+c][p]
__device__ float g_W2[PP*36];        // [c][j*9+t]
__device__ float g_W3[768*COUT];     // [k=j*192+c][o]
__device__ float g_wmax[48];         // [stage*16+cand]
__device__ float g_probs[48];        // [stage*16+cand]
__device__ float g_sum1[PP], g_ssq1[PP];
__device__ float g_sum2[PP], g_ssq2[PP];
__device__ float g_sum3[COUT], g_ssq3[COUT];

__device__ __forceinline__ float tanh_acc(float w) {
    return (float)tanh((double)w);   // correctly-rounded fp32 tanh
}

// ---------------- kernel 1: zero stats + softmax probs ---------------------
__global__ void k_init(const float* __restrict__ p1, const float* __restrict__ p2,
                       const float* __restrict__ p3) {
    int t = threadIdx.x;
    if (t < PP)   { g_sum1[t]=0.f; g_ssq1[t]=0.f; g_sum2[t]=0.f; g_ssq2[t]=0.f; }
    if (t < COUT) { g_sum3[t]=0.f; g_ssq3[t]=0.f; }
    if (t < 3) {
        const float* p = (t==0)?p1:((t==1)?p2:p3);
        float mx = -1e30f;
        for (int i=0;i<16;i++) mx = fmaxf(mx, p[i]);
        float e[16], s=0.f;
        for (int i=0;i<16;i++){ e[i]=expf(p[i]-mx); s+=e[i]; }
        float inv = 1.f/s;
        for (int i=0;i<16;i++) g_probs[t*16+i] = e[i]*inv;
    }
}

// ---------------- kernel 2: per-candidate max|tanh(w)| ---------------------
__global__ void k_wmax(const float* __restrict__ w1, const float* __restrict__ w2,
                       const float* __restrict__ w3) {
    int bi = blockIdx.x;
    int stage = bi >> 4, cand = bi & 15;
    const float* w; int E;
    if (stage==0)      { w = w1 + cand*PP*CIN;  E = PP*CIN;  }
    else if (stage==1) { w = w2 + cand*PP*9;    E = PP*9;    }
    else               { w = w3 + cand*COUT*PP; E = COUT*PP; }
    float m = 0.f;
    for (int i=threadIdx.x;i<E;i+=blockDim.x) m = fmaxf(m, fabsf(tanh_acc(w[i])));
    for (int o=16;o;o>>=1) m = fmaxf(m, __shfl_down_sync(0xffffffffu, m, o));
    __shared__ float sm[8];
    if ((threadIdx.x & 31)==0) sm[threadIdx.x>>5] = m;
    __syncthreads();
    if (threadIdx.x==0) {
        for (int i=1;i<8;i++) m = fmaxf(m, sm[i]);
        g_wmax[bi] = m;
    }
}

// ---------------- kernel 3: combined (prob-weighted quantized) weights -----
__global__ void k_combine(const float* __restrict__ w1, const float* __restrict__ w2,
                          const float* __restrict__ w3, int stage) {
    const float nv[4]  = {3.f,7.f,15.f,31.f};
    const float niv[4] = {1.f/3.f,1.f/7.f,1.f/15.f,1.f/31.f};
    int e = blockIdx.x*blockDim.x + threadIdx.x;
    if (stage==0) {
        if (e >= 4*PP*CIN) return;
        int c = e & 31, p = (e>>5) % PP, j = e/(32*PP);
        float acc = 0.f;
        #pragma unroll
        for (int i=0;i<4;i++) {
            int idx = 4*i+j;
            float t  = tanh_acc(w1[(idx*PP + p)*CIN + c]);
            float tn = t/(2.f*g_wmax[idx]) + 0.5f;
            float q  = rintf(tn*nv[i])*niv[i];
            acc += g_probs[idx]*(2.f*q - 1.f);
        }
        g_W1[(j*32 + c)*PP + p] = acc;
    } else if (stage==1) {
        if (e >= 4*PP*9) return;
        int t9 = e % 9, c = (e/9) % PP, j = e/(9*PP);
        float acc = 0.f;
        #pragma unroll
        for (int i=0;i<4;i++) {
            int idx = 4*i+j;
            float t  = tanh_acc(w2[(idx*PP + c)*9 + t9]);
            float tn = t/(2.f*g_wmax[16+idx]) + 0.5f;
            float q  = rintf(tn*nv[i])*niv[i];
            acc += g_probs[16+idx]*(2.f*q - 1.f);
        }
        g_W2[c*36 + j*9 + t9] = acc;
    } else {
        if (e >= 4*COUT*PP) return;
        int c = e % PP, o = (e/PP) % COUT, j = e/(PP*COUT);
        float acc = 0.f;
        #pragma unroll
        for (int i=0;i<4;i++) {
            int idx = 4*i+j;
            float t  = tanh_acc(w3[(idx*COUT + o)*PP + c]);
            float tn = t/(2.f*g_wmax[32+idx]) + 0.5f;
            float q  = rintf(tn*nv[i])*niv[i];
            acc += g_probs[32+idx]*(2.f*q - 1.f);
        }
        g_W3[(j*PP + c)*COUT + o] = acc;
    }
}

// ---------------- stage 1: 192x128 GEMM over pixels + BN stats -------------
__global__ __launch_bounds__(256) void k_stage1(const float* __restrict__ x) {
    __shared__ float xq[128][64];   // 4 quantized versions of x tile  (32 KB)
    __shared__ float ws[32][64];    // weight k-chunk                   (8 KB)
    int n0 = blockIdx.x * 64;
    int p0 = blockIdx.y * 64;
    int b = n0 >> 10, hw0 = n0 & 1023;
    int tid = threadIdx.x;
    // fill quantized activations (clip [0,1], 4 bitwidths)
    for (int idx = tid; idx < CIN*64; idx += 256) {
        int c = idx >> 6, px = idx & 63;
        float u  = x[(b*CIN + c)*HW + hw0 + px];
        float uc = fminf(fmaxf(u, 0.f), 1.f);
        xq[c     ][px] = rintf(uc*3.f )*(1.f/3.f );
        xq[32 + c][px] = rintf(uc*7.f )*(1.f/7.f );
        xq[64 + c][px] = rintf(uc*15.f)*(1.f/15.f);
        xq[96 + c][px] = rintf(uc*31.f)*(1.f/31.f);
    }
    float acc[4][4] = {};
    int tx = tid & 15, ty = tid >> 4;
    for (int ch = 0; ch < 4; ch++) {
        int k0 = ch * 32;
        __syncthreads();
        for (int idx = tid; idx < 32*64; idx += 256) {
            int kk = idx >> 6, pp = idx & 63;
            ws[kk][pp] = g_W1[(k0+kk)*PP + p0 + pp];
        }
        __syncthreads();
        #pragma unroll
        for (int kk = 0; kk < 32; kk++) {
            float4 a = *(const float4*)&xq[k0+kk][tx*4];
            float4 w = *(const float4*)&ws[kk][ty*4];
            acc[0][0] += w.x*a.x; acc[0][1] += w.x*a.y; acc[0][2] += w.x*a.z; acc[0][3] += w.x*a.w;
            acc[1][0] += w.y*a.x; acc[1][1] += w.y*a.y; acc[1][2] += w.y*a.z; acc[1][3] += w.y*a.w;
            acc[2][0] += w.z*a.x; acc[2][1] += w.z*a.y; acc[2][2] += w.z*a.z; acc[2][3] += w.z*a.w;
            acc[3][0] += w.w*a.x; acc[3][1] += w.w*a.y; acc[3][2] += w.w*a.z; acc[3][3] += w.w*a.w;
        }
    }
    #pragma unroll
    for (int r = 0; r < 4; r++) {
        int p = p0 + ty*4 + r;
        float4 v = make_float4(acc[r][0], acc[r][1], acc[r][2], acc[r][3]);
        *(float4*)&g_y1[(b*PP + p)*HW + hw0 + tx*4] = v;
        float s  = v.x + v.y + v.z + v.w;
        float ss = v.x*v.x + v.y*v.y + v.z*v.z + v.w*v.w;
        for (int o = 8; o; o >>= 1) {
            s  += __shfl_down_sync(0xffffffffu, s,  o, 16);
            ss += __shfl_down_sync(0xffffffffu, ss, o, 16);
        }
        if (tx == 0) { atomicAdd(&g_sum1[p], s); atomicAdd(&g_ssq1[p], ss); }
    }
}

// ---------------- stage 2: depthwise 3x3 (BN1+ReLU+quant fused) ------------
__global__ __launch_bounds__(256) void k_stage2(const float* __restrict__ g1,
                                                const float* __restrict__ b1) {
    int bx = blockIdx.x;
    int c = bx % PP, b = bx / PP;
    __shared__ float qp[4][34*34];  // quantized planes with zero apron
    __shared__ float wv[36];
    __shared__ float ab[2];
    int tid = threadIdx.x;
    if (tid == 0) {
        float mean = g_sum1[c] * (1.f/NCNT);
        float var  = g_ssq1[c] * (1.f/NCNT) - mean*mean;
        float A = g1[c] * rsqrtf(var + EPSF);
        ab[0] = A; ab[1] = b1[c] - mean*A;
    }
    if (tid < 36) wv[tid] = g_W2[c*36 + tid];
    for (int i = tid; i < 4*34*34; i += 256) (&qp[0][0])[i] = 0.f;
    __syncthreads();
    float A = ab[0], Bc = ab[1];
    const float* src = g_y1 + (b*PP + c)*HW;
    for (int i = tid; i < 1024; i += 256) {
        int h = i >> 5, w = i & 31;
        float u = src[i];
        float v = fminf(fmaxf(A*u + Bc, 0.f), 1.f);
        int o = (h+1)*34 + (w+1);
        qp[0][o] = rintf(v*3.f )*(1.f/3.f );
        qp[1][o] = rintf(v*7.f )*(1.f/7.f );
        qp[2][o] = rintf(v*15.f)*(1.f/15.f);
        qp[3][o] = rintf(v*31.f)*(1.f/31.f);
    }
    __syncthreads();
    float* dst = g_y2 + (b*PP + c)*HW;
    float ls = 0.f, lss = 0.f;
    for (int i = tid; i < 1024; i += 256) {
        int h = i >> 5, w = i & 31;
        float acc = 0.f;
        #pragma unroll
        for (int j = 0; j < 4; j++) {
            const float* q  = &qp[j][h*34 + w];
            const float* wj = wv + j*9;
            acc += wj[0]*q[0]  + wj[1]*q[1]  + wj[2]*q[2]
                 + wj[3]*q[34] + wj[4]*q[35] + wj[5]*q[36]
                 + wj[6]*q[68] + wj[7]*q[69] + wj[8]*q[70];
        }
        dst[i] = acc;
        ls += acc; lss += acc*acc;
    }
    for (int o = 16; o; o >>= 1) {
        ls  += __shfl_down_sync(0xffffffffu, ls,  o);
        lss += __shfl_down_sync(0xffffffffu, lss, o);
    }
    __shared__ float rs[8], rss[8];
    if ((tid & 31) == 0) { rs[tid>>5] = ls; rss[tid>>5] = lss; }
    __syncthreads();
    if (tid == 0) {
        float s = 0.f, ss = 0.f;
        for (int i = 0; i < 8; i++) { s += rs[i]; ss += rss[i]; }
        atomicAdd(&g_sum2[c], s); atomicAdd(&g_ssq2[c], ss);
    }
}

// ---------------- stage 3: 32x768 GEMM (BN2+ReLU+quant fused) --------------
__global__ __launch_bounds__(256) void k_stage3(const float* __restrict__ g2,
                                                const float* __restrict__ b2) {
    __shared__ float aq[64][128];   // 32 KB quantized activation chunk
    __shared__ float wsm[64][32];   // 8 KB weight chunk
    __shared__ float As[PP], Bs[PP];
    int tid = threadIdx.x;
    int n0 = blockIdx.x * 128;
    int b = n0 >> 10, hw0 = n0 & 1023;
    for (int c = tid; c < PP; c += 256) {
        float mean = g_sum2[c] * (1.f/NCNT);
        float var  = g_ssq2[c] * (1.f/NCNT) - mean*mean;
        float A = g2[c] * rsqrtf(var + EPSF);
        As[c] = A; Bs[c] = b2[c] - mean*A;
    }
    float acc[4][4] = {};
    int tx = tid & 31, ty = tid >> 5;
    for (int cb = 0; cb < 12; cb++) {
        __syncthreads();
        for (int idx = tid; idx < 16*128; idx += 256) {
            int cl = idx >> 7, px = idx & 127;
            int c = cb*16 + cl;
            float u = g_y2[(b*PP + c)*HW + hw0 + px];
            float v = fminf(fmaxf(As[c]*u + Bs[c], 0.f), 1.f);
            aq[cl     ][px] = rintf(v*3.f )*(1.f/3.f );
            aq[16 + cl][px] = rintf(v*7.f )*(1.f/7.f );
            aq[32 + cl][px] = rintf(v*15.f)*(1.f/15.f);
            aq[48 + cl][px] = rintf(v*31.f)*(1.f/31.f);
        }
        for (int idx = tid; idx < 64*32; idx += 256) {
            int kk = idx >> 5, oo = idx & 31;
            int j = kk >> 4, cl = kk & 15;
            wsm[kk][oo] = g_W3[(j*PP + cb*16 + cl)*COUT + oo];
        }
        __syncthreads();
        #pragma unroll
        for (int kk = 0; kk < 64; kk++) {
            float4 a = *(const float4*)&aq[kk][tx*4];
            float4 w = *(const float4*)&wsm[kk][ty*4];
            acc[0][0] += w.x*a.x; acc[0][1] += w.x*a.y; acc[0][2] += w.x*a.z; acc[0][3] += w.x*a.w;
            acc[1][0] += w.y*a.x; acc[1][1] += w.y*a.y; acc[1][2] += w.y*a.z; acc[1][3] += w.y*a.w;
            acc[2][0] += w.z*a.x; acc[2][1] += w.z*a.y; acc[2][2] += w.z*a.z; acc[2][3] += w.z*a.w;
            acc[3][0] += w.w*a.x; acc[3][1] += w.w*a.y; acc[3][2] += w.w*a.z; acc[3][3] += w.w*a.w;
        }
    }
    #pragma unroll
    for (int r = 0; r < 4; r++) {
        int o = ty*4 + r;
        float4 v = make_float4(acc[r][0], acc[r][1], acc[r][2], acc[r][3]);
        *(float4*)&g_y3[(b*COUT + o)*HW + hw0 + tx*4] = v;
        float s  = v.x + v.y + v.z + v.w;
        float ss = v.x*v.x + v.y*v.y + v.z*v.z + v.w*v.w;
        for (int off = 16; off; off >>= 1) {
            s  += __shfl_down_sync(0xffffffffu, s,  off);
            ss += __shfl_down_sync(0xffffffffu, ss, off);
        }
        if (tx == 0) { atomicAdd(&g_sum3[o], s); atomicAdd(&g_ssq3[o], ss); }
    }
}

// ---------------- final: out = BN3(y3) + x ---------------------------------
__global__ __launch_bounds__(256) void k_final(const float* __restrict__ x,
                                               const float* __restrict__ g3,
                                               const float* __restrict__ b3,
                                               float* __restrict__ out) {
    __shared__ float As[COUT], Bs[COUT];
    int tid = threadIdx.x;
    if (tid < COUT) {
        float mean = g_sum3[tid] * (1.f/NCNT);
        float var  = g_ssq3[tid] * (1.f/NCNT) - mean*mean;
        float A = g3[tid] * rsqrtf(var + EPSF);
        As[tid] = A; Bs[tid] = b3[tid] - mean*A;
    }
    __syncthreads();
    int i4 = blockIdx.x * blockDim.x + tid;
    int total4 = BB*COUT*HW/4;
    if (i4 < total4) {
        int c = (i4 >> 8) & 31;
        float4 y  = ((const float4*)g_y3)[i4];
        float4 xi = ((const float4*)x)[i4];
        float A = As[c], Bv = Bs[c];
        float4 o;
        o.x = A*y.x + Bv + xi.x;
        o.y = A*y.y + Bv + xi.y;
        o.z = A*y.z + Bv + xi.z;
        o.w = A*y.w + Bv + xi.w;
        ((float4*)out)[i4] = o;
    }
}

// ---------------- launch ---------------------------------------------------
extern "C" void kernel_launch(void* const* d_in, const int* in_sizes, int n_in,
                              void* d_out, int out_size) {
    (void)in_sizes; (void)n_in; (void)out_size;
    const float* x  = (const float*)d_in[0];
    const float* w1 = (const float*)d_in[1];
    const float* w2 = (const float*)d_in[2];
    const float* w3 = (const float*)d_in[3];
    const float* p1 = (const float*)d_in[4];
    const float* p2 = (const float*)d_in[5];
    const float* p3 = (const float*)d_in[6];
    const float* g1 = (const float*)d_in[7];
    const float* b1 = (const float*)d_in[8];
    const float* g2 = (const float*)d_in[9];
    const float* b2 = (const float*)d_in[10];
    const float* g3 = (const float*)d_in[11];
    const float* b3 = (const float*)d_in[12];
    float* out = (float*)d_out;

    k_init<<<1, 256>>>(p1, p2, p3);
    k_wmax<<<48, 256>>>(w1, w2, w3);
    k_combine<<<(4*PP*CIN + 255)/256, 256>>>(w1, w2, w3, 0);
    k_combine<<<(4*PP*9   + 255)/256, 256>>>(w1, w2, w3, 1);
    k_combine<<<(4*COUT*PP+ 255)/256, 256>>>(w1, w2, w3, 2);
    k_stage1<<<dim3(NPIX/64, 3), 256>>>(x);
    k_stage2<<<BB*PP, 256>>>(g1, b1);
    k_stage3<<<NPIX/128, 256>>>(g2, b2);
    k_final<<<(BB*COUT*HW/4)/256, 256>>>(x, g3, b3, out);
}

// round 4
// speedup vs baseline: 1.0017x; 1.0017x over previous
#include <cuda_runtime.h>
#include <math.h>

// Problem dims
#define BB   256
#define CIN  32
#define HW   1024          // 32*32
#define PP   192
#define COUT 32
#define NPIX (BB*HW)       // 262144
#define NCNT 262144.0f
#define EPSF 1e-5f

// ---------------- scratch (device globals; no allocation allowed) ----------
__device__ float g_y1[BB*PP*HW];     // stage1 raw conv output (NCHW)
__device__ float g_y2[BB*PP*HW];     // stage2 raw conv output
__device__ float g_y3[BB*COUT*HW];   // stage3 raw conv output
__device__ float g_W1[128*PP];       // [k=j*32+c][p]
__device__ float g_W2[PP*36];        // [c][j*9+t]
__device__ float g_W3[768*COUT];     // [k=j*192+c][o]
__device__ float g_wmax[48];         // [stage*16+cand]
__device__ float g_probs[48];        // [stage*16+cand]
__device__ float g_sum1[PP], g_ssq1[PP];
__device__ float g_sum2[PP], g_ssq2[PP];
__device__ float g_sum3[COUT], g_ssq3[COUT];

__device__ __forceinline__ float tanh_acc(float w) {
    return (float)tanh((double)w);   // correctly-rounded fp32 tanh
}

// ---------------- kernel 1: zero stats + softmax probs ---------------------
__global__ void k_init(const float* __restrict__ p1, const float* __restrict__ p2,
                       const float* __restrict__ p3) {
    int t = threadIdx.x;
    if (t < PP)   { g_sum1[t]=0.f; g_ssq1[t]=0.f; g_sum2[t]=0.f; g_ssq2[t]=0.f; }
    if (t < COUT) { g_sum3[t]=0.f; g_ssq3[t]=0.f; }
    if (t < 3) {
        const float* p = (t==0)?p1:((t==1)?p2:p3);
        float mx = -1e30f;
        for (int i=0;i<16;i++) mx = fmaxf(mx, p[i]);
        float e[16], s=0.f;
        for (int i=0;i<16;i++){ e[i]=expf(p[i]-mx); s+=e[i]; }
        float inv = 1.f/s;
        for (int i=0;i<16;i++) g_probs[t*16+i] = e[i]*inv;
    }
}

// ---------------- kernel 2: per-candidate max|tanh(w)| ---------------------
__global__ void k_wmax(const float* __restrict__ w1, const float* __restrict__ w2,
                       const float* __restrict__ w3) {
    int bi = blockIdx.x;
    int stage = bi >> 4, cand = bi & 15;
    const float* w; int E;
    if (stage==0)      { w = w1 + cand*PP*CIN;  E = PP*CIN;  }
    else if (stage==1) { w = w2 + cand*PP*9;    E = PP*9;    }
    else               { w = w3 + cand*COUT*PP; E = COUT*PP; }
    float m = 0.f;
    for (int i=threadIdx.x;i<E;i+=blockDim.x) m = fmaxf(m, fabsf(tanh_acc(w[i])));
    for (int o=16;o;o>>=1) m = fmaxf(m, __shfl_down_sync(0xffffffffu, m, o));
    __shared__ float sm[8];
    if ((threadIdx.x & 31)==0) sm[threadIdx.x>>5] = m;
    __syncthreads();
    if (threadIdx.x==0) {
        for (int i=1;i<8;i++) m = fmaxf(m, sm[i]);
        g_wmax[bi] = m;
    }
}

// ---------------- kernel 3: combined (prob-weighted quantized) weights -----
__global__ void k_combine(const float* __restrict__ w1, const float* __restrict__ w2,
                          const float* __restrict__ w3, int stage) {
    const float nv[4]  = {3.f,7.f,15.f,31.f};
    const float niv[4] = {1.f/3.f,1.f/7.f,1.f/15.f,1.f/31.f};
    int e = blockIdx.x*blockDim.x + threadIdx.x;
    if (stage==0) {
        if (e >= 4*PP*CIN) return;
        int c = e & 31, p = (e>>5) % PP, j = e/(32*PP);
        float acc = 0.f;
        #pragma unroll
        for (int i=0;i<4;i++) {
            int idx = 4*i+j;
            float t  = tanh_acc(w1[(idx*PP + p)*CIN + c]);
            float tn = t/(2.f*g_wmax[idx]) + 0.5f;
            float q  = rintf(tn*nv[i])*niv[i];
            acc += g_probs[idx]*(2.f*q - 1.f);
        }
        g_W1[(j*32 + c)*PP + p] = acc;
    } else if (stage==1) {
        if (e >= 4*PP*9) return;
        int t9 = e % 9, c = (e/9) % PP, j = e/(9*PP);
        float acc = 0.f;
        #pragma unroll
        for (int i=0;i<4;i++) {
            int idx = 4*i+j;
            float t  = tanh_acc(w2[(idx*PP + c)*9 + t9]);
            float tn = t/(2.f*g_wmax[16+idx]) + 0.5f;
            float q  = rintf(tn*nv[i])*niv[i];
            acc += g_probs[16+idx]*(2.f*q - 1.f);
        }
        g_W2[c*36 + j*9 + t9] = acc;
    } else {
        if (e >= 4*COUT*PP) return;
        int c = e % PP, o = (e/PP) % COUT, j = e/(PP*COUT);
        float acc = 0.f;
        #pragma unroll
        for (int i=0;i<4;i++) {
            int idx = 4*i+j;
            float t  = tanh_acc(w3[(idx*COUT + o)*PP + c]);
            float tn = t/(2.f*g_wmax[32+idx]) + 0.5f;
            float q  = rintf(tn*nv[i])*niv[i];
            acc += g_probs[32+idx]*(2.f*q - 1.f);
        }
        g_W3[(j*PP + c)*COUT + o] = acc;
    }
}

// ---------------- stage 1: 192x128 GEMM over pixels + BN stats -------------
__global__ __launch_bounds__(256) void k_stage1(const float* __restrict__ x) {
    __shared__ float xq[128][64];   // 4 quantized versions of x tile  (32 KB)
    __shared__ float ws[32][64];    // weight k-chunk                   (8 KB)
    int n0 = blockIdx.x * 64;
    int p0 = blockIdx.y * 64;
    int b = n0 >> 10, hw0 = n0 & 1023;
    int tid = threadIdx.x;
    // fill quantized activations (clip [0,1], 4 bitwidths)
    for (int idx = tid; idx < CIN*64; idx += 256) {
        int c = idx >> 6, px = idx & 63;
        float u  = x[(b*CIN + c)*HW + hw0 + px];
        float uc = fminf(fmaxf(u, 0.f), 1.f);
        xq[c     ][px] = rintf(uc*3.f )*(1.f/3.f );
        xq[32 + c][px] = rintf(uc*7.f )*(1.f/7.f );
        xq[64 + c][px] = rintf(uc*15.f)*(1.f/15.f);
        xq[96 + c][px] = rintf(uc*31.f)*(1.f/31.f);
    }
    float acc[4][4] = {};
    int tx = tid & 15, ty = tid >> 4;
    for (int ch = 0; ch < 4; ch++) {
        int k0 = ch * 32;
        __syncthreads();
        for (int idx = tid; idx < 32*64; idx += 256) {
            int kk = idx >> 6, pp = idx & 63;
            ws[kk][pp] = g_W1[(k0+kk)*PP + p0 + pp];
        }
        __syncthreads();
        #pragma unroll
        for (int kk = 0; kk < 32; kk++) {
            float4 a = *(const float4*)&xq[k0+kk][tx*4];
            float4 w = *(const float4*)&ws[kk][ty*4];
            acc[0][0] += w.x*a.x; acc[0][1] += w.x*a.y; acc[0][2] += w.x*a.z; acc[0][3] += w.x*a.w;
            acc[1][0] += w.y*a.x; acc[1][1] += w.y*a.y; acc[1][2] += w.y*a.z; acc[1][3] += w.y*a.w;
            acc[2][0] += w.z*a.x; acc[2][1] += w.z*a.y; acc[2][2] += w.z*a.z; acc[2][3] += w.z*a.w;
            acc[3][0] += w.w*a.x; acc[3][1] += w.w*a.y; acc[3][2] += w.w*a.z; acc[3][3] += w.w*a.w;
        }
    }
    #pragma unroll
    for (int r = 0; r < 4; r++) {
        int p = p0 + ty*4 + r;
        float4 v = make_float4(acc[r][0], acc[r][1], acc[r][2], acc[r][3]);
        *(float4*)&g_y1[(b*PP + p)*HW + hw0 + tx*4] = v;
        float s  = v.x + v.y + v.z + v.w;
        float ss = v.x*v.x + v.y*v.y + v.z*v.z + v.w*v.w;
        for (int o = 8; o; o >>= 1) {
            s  += __shfl_down_sync(0xffffffffu, s,  o, 16);
            ss += __shfl_down_sync(0xffffffffu, ss, o, 16);
        }
        if (tx == 0) { atomicAdd(&g_sum1[p], s); atomicAdd(&g_ssq1[p], ss); }
    }
}

// ---------------- stage 2: depthwise 3x3 (BN1+ReLU+quant fused) ------------
__global__ __launch_bounds__(256) void k_stage2(const float* __restrict__ g1,
                                                const float* __restrict__ b1) {
    int bx = blockIdx.x;
    int c = bx % PP, b = bx / PP;
    __shared__ float qp[4][34*34];  // quantized planes with zero apron
    __shared__ float wv[36];
    __shared__ float ab[2];
    int tid = threadIdx.x;
    if (tid == 0) {
        float mean = g_sum1[c] * (1.f/NCNT);
        float var  = g_ssq1[c] * (1.f/NCNT) - mean*mean;
        float A = g1[c] * rsqrtf(var + EPSF);
        ab[0] = A; ab[1] = b1[c] - mean*A;
    }
    if (tid < 36) wv[tid] = g_W2[c*36 + tid];
    for (int i = tid; i < 4*34*34; i += 256) (&qp[0][0])[i] = 0.f;
    __syncthreads();
    float A = ab[0], Bc = ab[1];
    const float* src = g_y1 + (b*PP + c)*HW;
    for (int i = tid; i < 1024; i += 256) {
        int h = i >> 5, w = i & 31;
        float u = src[i];
        float v = fminf(fmaxf(A*u + Bc, 0.f), 1.f);
        int o = (h+1)*34 + (w+1);
        qp[0][o] = rintf(v*3.f )*(1.f/3.f );
        qp[1][o] = rintf(v*7.f )*(1.f/7.f );
        qp[2][o] = rintf(v*15.f)*(1.f/15.f);
        qp[3][o] = rintf(v*31.f)*(1.f/31.f);
    }
    __syncthreads();
    float* dst = g_y2 + (b*PP + c)*HW;
    float ls = 0.f, lss = 0.f;
    for (int i = tid; i < 1024; i += 256) {
        int h = i >> 5, w = i & 31;
        float acc = 0.f;
        #pragma unroll
        for (int j = 0; j < 4; j++) {
            const float* q  = &qp[j][h*34 + w];
            const float* wj = wv + j*9;
            acc += wj[0]*q[0]  + wj[1]*q[1]  + wj[2]*q[2]
                 + wj[3]*q[34] + wj[4]*q[35] + wj[5]*q[36]
                 + wj[6]*q[68] + wj[7]*q[69] + wj[8]*q[70];
        }
        dst[i] = acc;
        ls += acc; lss += acc*acc;
    }
    for (int o = 16; o; o >>= 1) {
        ls  += __shfl_down_sync(0xffffffffu, ls,  o);
        lss += __shfl_down_sync(0xffffffffu, lss, o);
    }
    __shared__ float rs[8], rss[8];
    if ((tid & 31) == 0) { rs[tid>>5] = ls; rss[tid>>5] = lss; }
    __syncthreads();
    if (tid == 0) {
        float s = 0.f, ss = 0.f;
        for (int i = 0; i < 8; i++) { s += rs[i]; ss += rss[i]; }
        atomicAdd(&g_sum2[c], s); atomicAdd(&g_ssq2[c], ss);
    }
}

// ---------------- stage 3: 32x768 GEMM (BN2+ReLU+quant fused) --------------
__global__ __launch_bounds__(256) void k_stage3(const float* __restrict__ g2,
                                                const float* __restrict__ b2) {
    __shared__ float aq[64][128];   // 32 KB quantized activation chunk
    __shared__ float wsm[64][32];   // 8 KB weight chunk
    __shared__ float As[PP], Bs[PP];
    int tid = threadIdx.x;
    int n0 = blockIdx.x * 128;
    int b = n0 >> 10, hw0 = n0 & 1023;
    for (int c = tid; c < PP; c += 256) {
        float mean = g_sum2[c] * (1.f/NCNT);
        float var  = g_ssq2[c] * (1.f/NCNT) - mean*mean;
        float A = g2[c] * rsqrtf(var + EPSF);
        As[c] = A; Bs[c] = b2[c] - mean*A;
    }
    float acc[4][4] = {};
    int tx = tid & 31, ty = tid >> 5;
    for (int cb = 0; cb < 12; cb++) {
        __syncthreads();
        for (int idx = tid; idx < 16*128; idx += 256) {
            int cl = idx >> 7, px = idx & 127;
            int c = cb*16 + cl;
            float u = g_y2[(b*PP + c)*HW + hw0 + px];
            float v = fminf(fmaxf(As[c]*u + Bs[c], 0.f), 1.f);
            aq[cl     ][px] = rintf(v*3.f )*(1.f/3.f );
            aq[16 + cl][px] = rintf(v*7.f )*(1.f/7.f );
            aq[32 + cl][px] = rintf(v*15.f)*(1.f/15.f);
            aq[48 + cl][px] = rintf(v*31.f)*(1.f/31.f);
        }
        for (int idx = tid; idx < 64*32; idx += 256) {
            int kk = idx >> 5, oo = idx & 31;
            int j = kk >> 4, cl = kk & 15;
            wsm[kk][oo] = g_W3[(j*PP + cb*16 + cl)*COUT + oo];
        }
        __syncthreads();
        #pragma unroll
        for (int kk = 0; kk < 64; kk++) {
            float4 a = *(const float4*)&aq[kk][tx*4];
            float4 w = *(const float4*)&wsm[kk][ty*4];
            acc[0][0] += w.x*a.x; acc[0][1] += w.x*a.y; acc[0][2] += w.x*a.z; acc[0][3] += w.x*a.w;
            acc[1][0] += w.y*a.x; acc[1][1] += w.y*a.y; acc[1][2] += w.y*a.z; acc[1][3] += w.y*a.w;
            acc[2][0] += w.z*a.x; acc[2][1] += w.z*a.y; acc[2][2] += w.z*a.z; acc[2][3] += w.z*a.w;
            acc[3][0] += w.w*a.x; acc[3][1] += w.w*a.y; acc[3][2] += w.w*a.z; acc[3][3] += w.w*a.w;
        }
    }
    #pragma unroll
    for (int r = 0; r < 4; r++) {
        int o = ty*4 + r;
        float4 v = make_float4(acc[r][0], acc[r][1], acc[r][2], acc[r][3]);
        *(float4*)&g_y3[(b*COUT + o)*HW + hw0 + tx*4] = v;
        float s  = v.x + v.y + v.z + v.w;
        float ss = v.x*v.x + v.y*v.y + v.z*v.z + v.w*v.w;
        for (int off = 16; off; off >>= 1) {
            s  += __shfl_down_sync(0xffffffffu, s,  off);
            ss += __shfl_down_sync(0xffffffffu, ss, off);
        }
        if (tx == 0) { atomicAdd(&g_sum3[o], s); atomicAdd(&g_ssq3[o], ss); }
    }
}

// ---------------- final: out = BN3(y3) + x ---------------------------------
__global__ __launch_bounds__(256) void k_final(const float* __restrict__ x,
                                               const float* __restrict__ g3,
                                               const float* __restrict__ b3,
                                               float* __restrict__ out) {
    __shared__ float As[COUT], Bs[COUT];
    int tid = threadIdx.x;
    if (tid < COUT) {
        float mean = g_sum3[tid] * (1.f/NCNT);
        float var  = g_ssq3[tid] * (1.f/NCNT) - mean*mean;
        float A = g3[tid] * rsqrtf(var + EPSF);
        As[tid] = A; Bs[tid] = b3[tid] - mean*A;
    }
    __syncthreads();
    int i4 = blockIdx.x * blockDim.x + tid;
    int total4 = BB*COUT*HW/4;
    if (i4 < total4) {
        int c = (i4 >> 8) & 31;
        float4 y  = ((const float4*)g_y3)[i4];
        float4 xi = ((const float4*)x)[i4];
        float A = As[c], Bv = Bs[c];
        float4 o;
        o.x = A*y.x + Bv + xi.x;
        o.y = A*y.y + Bv + xi.y;
        o.z = A*y.z + Bv + xi.z;
        o.w = A*y.w + Bv + xi.w;
        ((float4*)out)[i4] = o;
    }
}

// ---------------- launch ---------------------------------------------------
extern "C" void kernel_launch(void* const* d_in, const int* in_sizes, int n_in,
                              void* d_out, int out_size) {
    (void)in_sizes; (void)n_in; (void)out_size;
    const float* x  = (const float*)d_in[0];
    const float* w1 = (const float*)d_in[1];
    const float* w2 = (const float*)d_in[2];
    const float* w3 = (const float*)d_in[3];
    const float* p1 = (const float*)d_in[4];
    const float* p2 = (const float*)d_in[5];
    const float* p3 = (const float*)d_in[6];
    const float* g1 = (const float*)d_in[7];
    const float* b1 = (const float*)d_in[8];
    const float* g2 = (const float*)d_in[9];
    const float* b2 = (const float*)d_in[10];
    const float* g3 = (const float*)d_in[11];
    const float* b3 = (const float*)d_in[12];
    float* out = (float*)d_out;

    k_init<<<1, 256>>>(p1, p2, p3);
    k_wmax<<<48, 256>>>(w1, w2, w3);
    k_combine<<<(4*PP*CIN + 255)/256, 256>>>(w1, w2, w3, 0);
    k_combine<<<(4*PP*9   + 255)/256, 256>>>(w1, w2, w3, 1);
    k_combine<<<(4*COUT*PP+ 255)/256, 256>>>(w1, w2, w3, 2);
    k_stage1<<<dim3(NPIX/64, 3), 256>>>(x);
    k_stage2<<<BB*PP, 256>>>(g1, b1);
    k_stage3<<<NPIX/128, 256>>>(g2, b2);
    k_final<<<(BB*COUT*HW/4)/256, 256>>>(x, g3, b3, out);
}